// round 14
// baseline (speedup 1.0000x reference)
#include <cuda_runtime.h>
#include <cuda_fp16.h>
#include <cstdint>

#define NMAX 100000
#define EMAX 1600000
#define GMAX 128
#define HID  64
#define CAP  64      // ELL width; in-deg ~ Poisson(16), P(overflow) ~ 1e-13

// ---------------- scratch (no allocations allowed) ----------------
__device__ float  g_dinv[NMAX];
__device__ int    g_deg[NMAX];
__device__ int    g_ell[(size_t)NMAX * CAP];
__device__ __half g_z1h[(size_t)NMAX * HID];   // z1 = (x@W1)*dinv, fp16
__device__ __half g_z2h[(size_t)NMAX * HID];   // z2, fp16
__device__ float  g_pool[GMAX * HID];
__device__ float  g_cnt[GMAX];

// ---------------- helpers ----------------
__device__ __forceinline__ void acc_half8(float* a, uint4 v) {
    const __half2* h = (const __half2*)&v;
    float2 f0 = __half22float2(h[0]);
    float2 f1 = __half22float2(h[1]);
    float2 f2 = __half22float2(h[2]);
    float2 f3 = __half22float2(h[3]);
    a[0] += f0.x; a[1] += f0.y; a[2] += f1.x; a[3] += f1.y;
    a[4] += f2.x; a[5] += f2.y; a[6] += f3.x; a[7] += f3.y;
}
__device__ __forceinline__ uint4 pack_half8(const float* f) {
    __half2 h[4];
    h[0] = __floats2half2_rn(f[0], f[1]);
    h[1] = __floats2half2_rn(f[2], f[3]);
    h[2] = __floats2half2_rn(f[4], f[5]);
    h[3] = __floats2half2_rn(f[6], f[7]);
    return *(uint4*)h;
}
__device__ __forceinline__ void ldsm_x4(uint32_t* r, uint32_t addr) {
    asm volatile("ldmatrix.sync.aligned.m8n8.x4.shared.b16 {%0,%1,%2,%3}, [%4];"
                 : "=r"(r[0]), "=r"(r[1]), "=r"(r[2]), "=r"(r[3]) : "r"(addr));
}
__device__ __forceinline__ void ldsm_x4_t(uint32_t* r, uint32_t addr) {
    asm volatile("ldmatrix.sync.aligned.m8n8.x4.trans.shared.b16 {%0,%1,%2,%3}, [%4];"
                 : "=r"(r[0]), "=r"(r[1]), "=r"(r[2]), "=r"(r[3]) : "r"(addr));
}
__device__ __forceinline__ void mma16816(float* c, const uint32_t* a,
                                         uint32_t b0, uint32_t b1) {
    asm volatile(
        "mma.sync.aligned.m16n8k16.row.col.f32.f16.f16.f32 "
        "{%0,%1,%2,%3},{%4,%5,%6,%7},{%8,%9},{%0,%1,%2,%3};"
        : "+f"(c[0]), "+f"(c[1]), "+f"(c[2]), "+f"(c[3])
        : "r"(a[0]), "r"(a[1]), "r"(a[2]), "r"(a[3]), "r"(b0), "r"(b1));
}
__device__ __forceinline__ uint2 split_pack4(float4 v) {
    __half h0 = __float2half(v.x), h1 = __float2half(v.y);
    __half h2 = __float2half(v.z), h3 = __float2half(v.w);
    uint2 r;
    r.x = (uint32_t)__half_as_ushort(h0) | ((uint32_t)__half_as_ushort(h1) << 16);
    r.y = (uint32_t)__half_as_ushort(h2) | ((uint32_t)__half_as_ushort(h3) << 16);
    return r;
}

// ================= graph build (ELL, one edge pass) =================
__global__ void k_init(int n) {
    int i = blockIdx.x * blockDim.x + threadIdx.x;
    if (i < n) g_deg[i] = 0;
    if (i < GMAX * HID) g_pool[i] = 0.f;
    if (i < GMAX) g_cnt[i] = 0.f;
}
__global__ void k_ell_fill(const int* __restrict__ src,
                           const int* __restrict__ dst, int E) {
    int e = blockIdx.x * blockDim.x + threadIdx.x;
    if (e >= E) return;
    int d = dst[e];
    int p = atomicAdd(&g_deg[d], 1);
    g_ell[(size_t)d * CAP + p] = src[e];
}
__global__ void k_dinv(int n) {
    int i = blockIdx.x * blockDim.x + threadIdx.x;
    if (i < n) g_dinv[i] = rsqrtf((float)g_deg[i] + 1.0f);
}

// ================= tensor-core GEMM1 (plain fp16 HMMA) =================
// z1[node,:] = (x[node,:] @ W1) * dinv[node] -> fp16
// smem: padded 72-half rows (144B stride -> ldmatrix conflict-free).
#define SW 72
#define OFF_WH 0
#define OFF_AH 18432
#define SM_G1  36864

__global__ void __launch_bounds__(256)
k_gemm1_mma(const float* __restrict__ X,
            const float* __restrict__ Wg,     // [128][64] fp32
            __half* __restrict__ Zh, int n) {
    extern __shared__ char sm[];
    const uint32_t sbase = (uint32_t)__cvta_generic_to_shared(sm);
    const int tid  = threadIdx.x;
    const int wid  = tid >> 5;
    const int lane = tid & 31;
    const int base = blockIdx.x * 128;

    // ---- stage W (all K=128 rows): fp32 -> fp16 ----
    for (int i = tid; i < 128 * 16; i += 256) {
        int row = i >> 4, c4 = i & 15;
        float4 w = ((const float4*)Wg)[i];
        *(uint2*)(sm + OFF_WH + (row * SW + c4 * 4) * 2) = split_pack4(w);
    }

    const int m0 = wid * 16;
    float c[8][4];
#pragma unroll
    for (int j = 0; j < 8; j++)
#pragma unroll
        for (int q = 0; q < 4; q++) c[j][q] = 0.f;

    const int a_row = m0 + (lane & 15);
    const int a_koff = (lane >> 4) << 3;
    const int b_rowoff = ((lane & 8) ? 8 : 0) + (lane & 7);
    const int b_noff = (lane >> 4) << 3;

#pragma unroll
    for (int ch = 0; ch < 2; ch++) {
        __syncthreads();
        for (int i = tid; i < 128 * 16; i += 256) {
            int m = i >> 4, c4 = i & 15;
            int node = base + m;
            float4 v = make_float4(0.f, 0.f, 0.f, 0.f);
            if (node < n)
                v = ((const float4*)(X + (size_t)node * 128 + ch * 64))[c4];
            *(uint2*)(sm + OFF_AH + (m * SW + c4 * 4) * 2) = split_pack4(v);
        }
        __syncthreads();

#pragma unroll
        for (int ks = 0; ks < 4; ks++) {
            const int k0l = ks * 16;
            const int k0g = ch * 64 + k0l;

            uint32_t ah[4];
            ldsm_x4(ah, sbase + OFF_AH + (a_row * SW + k0l + a_koff) * 2);

            const int b_row = k0g + b_rowoff;
#pragma unroll
            for (int np = 0; np < 4; np++) {
                uint32_t bh[4];
                ldsm_x4_t(bh, sbase + OFF_WH + (b_row * SW + np * 16 + b_noff) * 2);
                mma16816(c[2 * np],     ah, bh[0], bh[1]);
                mma16816(c[2 * np + 1], ah, bh[2], bh[3]);
            }
        }
    }

    // ---- epilogue: scale by dinv, pack fp16, store ----
    const int r0 = m0 + (lane >> 2);
    const int cc = (lane & 3) * 2;
    int node0 = base + r0;
    int node1 = node0 + 8;
    float d0 = (node0 < n) ? g_dinv[node0] : 0.f;
    float d1 = (node1 < n) ? g_dinv[node1] : 0.f;
#pragma unroll
    for (int j = 0; j < 8; j++) {
        int col = j * 8 + cc;
        if (node0 < n) {
            __half2 h = __floats2half2_rn(c[j][0] * d0, c[j][1] * d0);
            *(__half2*)(Zh + (size_t)node0 * HID + col) = h;
        }
        if (node1 < n) {
            __half2 h = __floats2half2_rn(c[j][2] * d1, c[j][3] * d1);
            *(__half2*)(Zh + (size_t)node1 * HID + col) = h;
        }
    }
}

// ---- split-degree gather core: 16 threads/node (2 subs x 8 col-lanes) ----
// sub 0 gathers edges [0,h) + self term; sub 1 gathers [h,deg).
// Caller combines subs via shfl_xor(8).
__device__ __forceinline__ void gather_half(float* a, const uint4* z16,
                                            int node, int sub, int jg) {
    if (sub == 0)
        acc_half8(a, __ldg(z16 + (size_t)node * 8 + jg));     // self term

    const int dg = __ldg(g_deg + node);
    int h = ((dg + 7) >> 3) << 2;            // half, multiple of 4
    if (h > dg) h = dg;
    const int lo = sub ? h : 0;
    const int hi = sub ? dg : h;
    const int* ep = g_ell + (size_t)node * CAP;

    int i = lo;
    for (; i + 4 <= hi; i += 4) {
        int4 s4 = __ldg((const int4*)(ep + i));
        uint4 v0 = __ldg(z16 + (size_t)s4.x * 8 + jg);
        uint4 v1 = __ldg(z16 + (size_t)s4.y * 8 + jg);
        uint4 v2 = __ldg(z16 + (size_t)s4.z * 8 + jg);
        uint4 v3 = __ldg(z16 + (size_t)s4.w * 8 + jg);
        acc_half8(a, v0); acc_half8(a, v1);
        acc_half8(a, v2); acc_half8(a, v3);
    }
    for (; i < hi; i++) {
        int s0 = __ldg(ep + i);
        acc_half8(a, __ldg(z16 + (size_t)s0 * 8 + jg));
    }
}

// ========== FUSED: aggregate-1 + input-transform + GEMM2 ==========
__global__ void __launch_bounds__(256)
k_agg_gemm2(const __half* __restrict__ z1h,
            const float* __restrict__ W2,
            const float* __restrict__ b1,
            __half* __restrict__ Z2h, int n) {
    constexpr int BM = 128;
    constexpr int K  = 64;
    constexpr int S  = K + 4;
    extern __shared__ float smf[];
    float* Xs = smf;                 // [128][68]
    float* Ws = smf + BM * S;        // [64][64]
    float* bs = Ws + K * 64;         // [64]

    const int tid  = threadIdx.x;
    const int base = blockIdx.x * BM;

    for (int i = tid; i < K * 16; i += 256)
        ((float4*)Ws)[i] = ((const float4*)W2)[i];
    if (tid < 64) bs[tid] = b1[tid];

    const uint4* z16 = (const uint4*)z1h;
#pragma unroll
    for (int p = 0; p < 8; p++) {              // 128 nodes * 16 threads = 2048
        int t   = tid + p * 256;
        int m   = t >> 4;
        int sub = (t >> 3) & 1;
        int jg  = t & 7;
        int node = base + m;
        float a[8] = {0.f,0.f,0.f,0.f,0.f,0.f,0.f,0.f};
        if (node < n) gather_half(a, z16, node, sub, jg);

        // combine subs (lanes t and t^8 share node & jg)
#pragma unroll
        for (int j = 0; j < 8; j++)
            a[j] += __shfl_xor_sync(0xffffffffu, a[j], 8);

        if (sub == 0) {
            if (node < n) {
                float dn = __ldg(g_dinv + node);
                int k0 = jg * 8;
#pragma unroll
                for (int j = 0; j < 8; j++)
                    a[j] = fmaxf(fmaf(a[j], dn, bs[k0 + j]), 0.f);
            } else {
#pragma unroll
                for (int j = 0; j < 8; j++) a[j] = 0.f;
            }
            *(float4*)(Xs + m * S + jg * 8)     = make_float4(a[0], a[1], a[2], a[3]);
            *(float4*)(Xs + m * S + jg * 8 + 4) = make_float4(a[4], a[5], a[6], a[7]);
        }
    }
    __syncthreads();

    // ---- phase B: tile GEMM, epilogue * dinv -> fp16 ----
    const int row0 = (tid >> 3) * 4;
    const int col0 = (tid & 7) * 8;

    float acc[4][8];
#pragma unroll
    for (int i = 0; i < 4; i++)
#pragma unroll
        for (int j = 0; j < 8; j++) acc[i][j] = 0.f;

#pragma unroll 4
    for (int k = 0; k < K; k++) {
        float a0 = Xs[(row0 + 0) * S + k];
        float a1 = Xs[(row0 + 1) * S + k];
        float a2 = Xs[(row0 + 2) * S + k];
        float a3 = Xs[(row0 + 3) * S + k];
        float4 blo = *(float4*)(Ws + k * 64 + col0);
        float4 bhi = *(float4*)(Ws + k * 64 + col0 + 4);
        float b[8] = {blo.x, blo.y, blo.z, blo.w, bhi.x, bhi.y, bhi.z, bhi.w};
#pragma unroll
        for (int j = 0; j < 8; j++) {
            acc[0][j] = fmaf(a0, b[j], acc[0][j]);
            acc[1][j] = fmaf(a1, b[j], acc[1][j]);
            acc[2][j] = fmaf(a2, b[j], acc[2][j]);
            acc[3][j] = fmaf(a3, b[j], acc[3][j]);
        }
    }

#pragma unroll
    for (int i = 0; i < 4; i++) {
        int node = base + row0 + i;
        if (node < n) {
            float di = g_dinv[node];
            float f[8];
#pragma unroll
            for (int j = 0; j < 8; j++) f[j] = acc[i][j] * di;
            *(uint4*)(Z2h + (size_t)node * HID + col0) = pack_half8(f);
        }
    }
}

// ============ aggregate-2 (split-degree) fused with mean pool ============
__global__ void k_agg_pool(const __half* __restrict__ zh,
                           const int* __restrict__ batch, int n) {
    int t    = blockIdx.x * blockDim.x + threadIdx.x;
    int node = t >> 4;
    int sub  = (t >> 3) & 1;
    int jg   = t & 7;

    const uint4* z16 = (const uint4*)zh;
    float a[8] = {0.f,0.f,0.f,0.f,0.f,0.f,0.f,0.f};
    if (node < n) gather_half(a, z16, node, sub, jg);

#pragma unroll
    for (int j = 0; j < 8; j++)
        a[j] += __shfl_xor_sync(0xffffffffu, a[j], 8);

    if (sub == 0 && node < n) {
        float di = g_dinv[node];
        float4 lo = make_float4(a[0]*di, a[1]*di, a[2]*di, a[3]*di);
        float4 hi = make_float4(a[4]*di, a[5]*di, a[6]*di, a[7]*di);
        int g = __ldg(batch + node);
        atomicAdd((float4*)(g_pool + g * HID + jg * 8), lo);
        atomicAdd((float4*)(g_pool + g * HID + jg * 8 + 4), hi);
        if (jg == 0) atomicAdd(&g_cnt[g], 1.0f);
    }
}

__global__ void k_finalize(float* __restrict__ out,
                           const float* __restrict__ b2) {
    int t = blockIdx.x * blockDim.x + threadIdx.x;
    if (t >= GMAX * HID) return;
    int g = t >> 6, j = t & 63;
    out[t] = g_pool[t] / fmaxf(g_cnt[g], 1.0f) + b2[j];
}

// ================= launch (single stream, serial) =================
extern "C" void kernel_launch(void* const* d_in, const int* in_sizes, int n_in,
                              void* d_out, int out_size) {
    const float* x     = (const float*)d_in[0];
    const int*   eidx  = (const int*)d_in[1];
    const int*   batch = (const int*)d_in[2];
    const float* W1    = (const float*)d_in[3];
    const float* b1    = (const float*)d_in[4];
    const float* W2    = (const float*)d_in[5];
    const float* b2    = (const float*)d_in[6];
    float*       out   = (float*)d_out;

    const int n = in_sizes[0] / 128;
    const int E = in_sizes[1] / 2;
    const int* src = eidx;
    const int* dst = eidx + E;

    __half *z1h, *z2h;
    cudaGetSymbolAddress((void**)&z1h, g_z1h);
    cudaGetSymbolAddress((void**)&z2h, g_z2h);

    const int B = 256;
    const int NBn = (n + 255) / 256;
    const int NBe = (E + 255) / 256;
    const int gemm_grid  = (n + 127) / 128;
    const int agg_grid16 = (n * 16 + B - 1) / B;

    const int smemF = (128 * (64 + 4) + 64 * 64 + 64) * 4;     // 51456 B
    cudaFuncSetAttribute(k_gemm1_mma,
                         cudaFuncAttributeMaxDynamicSharedMemorySize, SM_G1);
    cudaFuncSetAttribute(k_agg_gemm2,
                         cudaFuncAttributeMaxDynamicSharedMemorySize, smemF);

    // ELL build (1 edge pass) + dinv + pool zeroing
    k_init<<<NBn, B>>>(n);
    k_ell_fill<<<NBe, B>>>(src, dst, E);
    k_dinv<<<NBn, B>>>(n);

    // layer-1 GEMM on tensor cores: z1 = (x@W1)*dinv -> fp16
    k_gemm1_mma<<<gemm_grid, 256, SM_G1>>>(x, W1, z1h, n);

    // fused aggregate-1 + transform + GEMM2 -> z2 (fp16)
    k_agg_gemm2<<<gemm_grid, 256, smemF>>>(z1h, W2, b1, z2h, n);

    // aggregate-2 fused with mean pool
    k_agg_pool<<<agg_grid16, B>>>(z2h, batch, n);
    k_finalize<<<(GMAX * HID + B - 1) / B, B>>>(out, b2);
}

// round 15
// speedup vs baseline: 1.0605x; 1.0605x over previous
#include <cuda_runtime.h>
#include <cuda_fp16.h>
#include <cstdint>

#define NMAX 100000
#define EMAX 1600000
#define GMAX 128
#define HID  64
#define CAP  64      // ELL width; in-deg ~ Poisson(16), P(overflow) ~ 1e-13

// ---------------- scratch (no allocations allowed) ----------------
__device__ float  g_dinv[NMAX];
__device__ int    g_deg[NMAX];
__device__ int    g_ell[(size_t)NMAX * CAP];
__device__ __half g_z1h[(size_t)NMAX * HID];   // z1 = (x@W1)*dinv, fp16
__device__ __half g_z2h[(size_t)NMAX * HID];   // z2, fp16
__device__ float  g_pool[GMAX * HID];
__device__ float  g_cnt[GMAX];

// ---------------- helpers ----------------
__device__ __forceinline__ void acc_half8(float* a, uint4 v) {
    const __half2* h = (const __half2*)&v;
    float2 f0 = __half22float2(h[0]);
    float2 f1 = __half22float2(h[1]);
    float2 f2 = __half22float2(h[2]);
    float2 f3 = __half22float2(h[3]);
    a[0] += f0.x; a[1] += f0.y; a[2] += f1.x; a[3] += f1.y;
    a[4] += f2.x; a[5] += f2.y; a[6] += f3.x; a[7] += f3.y;
}
__device__ __forceinline__ uint4 pack_half8(const float* f) {
    __half2 h[4];
    h[0] = __floats2half2_rn(f[0], f[1]);
    h[1] = __floats2half2_rn(f[2], f[3]);
    h[2] = __floats2half2_rn(f[4], f[5]);
    h[3] = __floats2half2_rn(f[6], f[7]);
    return *(uint4*)h;
}
__device__ __forceinline__ void ldsm_x4(uint32_t* r, uint32_t addr) {
    asm volatile("ldmatrix.sync.aligned.m8n8.x4.shared.b16 {%0,%1,%2,%3}, [%4];"
                 : "=r"(r[0]), "=r"(r[1]), "=r"(r[2]), "=r"(r[3]) : "r"(addr));
}
__device__ __forceinline__ void ldsm_x4_t(uint32_t* r, uint32_t addr) {
    asm volatile("ldmatrix.sync.aligned.m8n8.x4.trans.shared.b16 {%0,%1,%2,%3}, [%4];"
                 : "=r"(r[0]), "=r"(r[1]), "=r"(r[2]), "=r"(r[3]) : "r"(addr));
}
__device__ __forceinline__ void mma16816(float* c, const uint32_t* a,
                                         uint32_t b0, uint32_t b1) {
    asm volatile(
        "mma.sync.aligned.m16n8k16.row.col.f32.f16.f16.f32 "
        "{%0,%1,%2,%3},{%4,%5,%6,%7},{%8,%9},{%0,%1,%2,%3};"
        : "+f"(c[0]), "+f"(c[1]), "+f"(c[2]), "+f"(c[3])
        : "r"(a[0]), "r"(a[1]), "r"(a[2]), "r"(a[3]), "r"(b0), "r"(b1));
}
__device__ __forceinline__ uint2 split_pack4(float4 v) {
    __half h0 = __float2half(v.x), h1 = __float2half(v.y);
    __half h2 = __float2half(v.z), h3 = __float2half(v.w);
    uint2 r;
    r.x = (uint32_t)__half_as_ushort(h0) | ((uint32_t)__half_as_ushort(h1) << 16);
    r.y = (uint32_t)__half_as_ushort(h2) | ((uint32_t)__half_as_ushort(h3) << 16);
    return r;
}

// ================= graph build (ELL, one edge pass) =================
__global__ void k_init(int n) {
    int i = blockIdx.x * blockDim.x + threadIdx.x;
    if (i < n) g_deg[i] = 0;
    if (i < GMAX * HID) g_pool[i] = 0.f;
    if (i < GMAX) g_cnt[i] = 0.f;
}
__global__ void k_ell_fill(const int* __restrict__ src,
                           const int* __restrict__ dst, int E) {
    int e = blockIdx.x * blockDim.x + threadIdx.x;
    if (e >= E) return;
    int d = dst[e];
    int p = atomicAdd(&g_deg[d], 1);
    g_ell[(size_t)d * CAP + p] = src[e];
}
__global__ void k_dinv(int n) {
    int i = blockIdx.x * blockDim.x + threadIdx.x;
    if (i < n) g_dinv[i] = rsqrtf((float)g_deg[i] + 1.0f);
}

// ================= tensor-core GEMM1 (plain fp16 HMMA) =================
// z1[node,:] = (x[node,:] @ W1) * dinv[node] -> fp16
// smem: padded 72-half rows (144B stride -> ldmatrix conflict-free).
#define SW 72
#define OFF_WH 0
#define OFF_AH 18432
#define SM_G1  36864

__global__ void __launch_bounds__(256)
k_gemm1_mma(const float* __restrict__ X,
            const float* __restrict__ Wg,     // [128][64] fp32
            __half* __restrict__ Zh, int n) {
    extern __shared__ char sm[];
    const uint32_t sbase = (uint32_t)__cvta_generic_to_shared(sm);
    const int tid  = threadIdx.x;
    const int wid  = tid >> 5;
    const int lane = tid & 31;
    const int base = blockIdx.x * 128;

    // ---- stage W (all K=128 rows): fp32 -> fp16 ----
    for (int i = tid; i < 128 * 16; i += 256) {
        int row = i >> 4, c4 = i & 15;
        float4 w = ((const float4*)Wg)[i];
        *(uint2*)(sm + OFF_WH + (row * SW + c4 * 4) * 2) = split_pack4(w);
    }

    const int m0 = wid * 16;
    float c[8][4];
#pragma unroll
    for (int j = 0; j < 8; j++)
#pragma unroll
        for (int q = 0; q < 4; q++) c[j][q] = 0.f;

    const int a_row = m0 + (lane & 15);
    const int a_koff = (lane >> 4) << 3;
    const int b_rowoff = ((lane & 8) ? 8 : 0) + (lane & 7);
    const int b_noff = (lane >> 4) << 3;

#pragma unroll
    for (int ch = 0; ch < 2; ch++) {
        __syncthreads();
        for (int i = tid; i < 128 * 16; i += 256) {
            int m = i >> 4, c4 = i & 15;
            int node = base + m;
            float4 v = make_float4(0.f, 0.f, 0.f, 0.f);
            if (node < n)
                v = ((const float4*)(X + (size_t)node * 128 + ch * 64))[c4];
            *(uint2*)(sm + OFF_AH + (m * SW + c4 * 4) * 2) = split_pack4(v);
        }
        __syncthreads();

#pragma unroll
        for (int ks = 0; ks < 4; ks++) {
            const int k0l = ks * 16;
            const int k0g = ch * 64 + k0l;

            uint32_t ah[4];
            ldsm_x4(ah, sbase + OFF_AH + (a_row * SW + k0l + a_koff) * 2);

            const int b_row = k0g + b_rowoff;
#pragma unroll
            for (int np = 0; np < 4; np++) {
                uint32_t bh[4];
                ldsm_x4_t(bh, sbase + OFF_WH + (b_row * SW + np * 16 + b_noff) * 2);
                mma16816(c[2 * np],     ah, bh[0], bh[1]);
                mma16816(c[2 * np + 1], ah, bh[2], bh[3]);
            }
        }
    }

    // ---- epilogue: scale by dinv, pack fp16, store ----
    const int r0 = m0 + (lane >> 2);
    const int cc = (lane & 3) * 2;
    int node0 = base + r0;
    int node1 = node0 + 8;
    float d0 = (node0 < n) ? g_dinv[node0] : 0.f;
    float d1 = (node1 < n) ? g_dinv[node1] : 0.f;
#pragma unroll
    for (int j = 0; j < 8; j++) {
        int col = j * 8 + cc;
        if (node0 < n) {
            __half2 h = __floats2half2_rn(c[j][0] * d0, c[j][1] * d0);
            *(__half2*)(Zh + (size_t)node0 * HID + col) = h;
        }
        if (node1 < n) {
            __half2 h = __floats2half2_rn(c[j][2] * d1, c[j][3] * d1);
            *(__half2*)(Zh + (size_t)node1 * HID + col) = h;
        }
    }
}

// ========== FUSED: aggregate-1 + input-transform + GEMM2 ==========
// Phase A (8 lanes/node, 16B fp16 each): S = z1[d] + Σ z1[s]  (fp32 acc)
//   x2 = relu(dinv[d]*S + b1) -> GEMM X-tile in smem (fp32).
// Phase B: z2 = (x2 @ W2) * dinv[d] -> fp16
__global__ void __launch_bounds__(256)
k_agg_gemm2(const __half* __restrict__ z1h,
            const float* __restrict__ W2,
            const float* __restrict__ b1,
            __half* __restrict__ Z2h, int n) {
    constexpr int BM = 128;
    constexpr int K  = 64;
    constexpr int S  = K + 4;
    extern __shared__ float smf[];
    float* Xs = smf;                 // [128][68]
    float* Ws = smf + BM * S;        // [64][64]
    float* bs = Ws + K * 64;         // [64]

    const int tid  = threadIdx.x;
    const int base = blockIdx.x * BM;

    for (int i = tid; i < K * 16; i += 256)
        ((float4*)Ws)[i] = ((const float4*)W2)[i];
    if (tid < 64) bs[tid] = b1[tid];

    const uint4* z16 = (const uint4*)z1h;
#pragma unroll
    for (int p = 0; p < 4; p++) {
        int t  = tid + p * 256;
        int m  = t >> 3;
        int jg = t & 7;
        int node = base + m;
        float a[8] = {0.f,0.f,0.f,0.f,0.f,0.f,0.f,0.f};
        if (node < n) {
            acc_half8(a, __ldg(z16 + (size_t)node * 8 + jg));

            const int dg = __ldg(g_deg + node);
            const int* ep = g_ell + (size_t)node * CAP;
            int i = 0;
            for (; i + 4 <= dg; i += 4) {
                int4 s4 = __ldg((const int4*)(ep + i));
                uint4 v0 = __ldg(z16 + (size_t)s4.x * 8 + jg);
                uint4 v1 = __ldg(z16 + (size_t)s4.y * 8 + jg);
                uint4 v2 = __ldg(z16 + (size_t)s4.z * 8 + jg);
                uint4 v3 = __ldg(z16 + (size_t)s4.w * 8 + jg);
                acc_half8(a, v0); acc_half8(a, v1);
                acc_half8(a, v2); acc_half8(a, v3);
            }
            for (; i < dg; i++) {
                int s0 = __ldg(ep + i);
                acc_half8(a, __ldg(z16 + (size_t)s0 * 8 + jg));
            }

            float dn = __ldg(g_dinv + node);
            int k0 = jg * 8;
#pragma unroll
            for (int j = 0; j < 8; j++)
                a[j] = fmaxf(fmaf(a[j], dn, bs[k0 + j]), 0.f);
        }
        *(float4*)(Xs + m * S + jg * 8)     = make_float4(a[0], a[1], a[2], a[3]);
        *(float4*)(Xs + m * S + jg * 8 + 4) = make_float4(a[4], a[5], a[6], a[7]);
    }
    __syncthreads();

    // ---- phase B: tile GEMM, epilogue * dinv -> fp16 ----
    const int row0 = (tid >> 3) * 4;
    const int col0 = (tid & 7) * 8;

    float acc[4][8];
#pragma unroll
    for (int i = 0; i < 4; i++)
#pragma unroll
        for (int j = 0; j < 8; j++) acc[i][j] = 0.f;

#pragma unroll 4
    for (int k = 0; k < K; k++) {
        float a0 = Xs[(row0 + 0) * S + k];
        float a1 = Xs[(row0 + 1) * S + k];
        float a2 = Xs[(row0 + 2) * S + k];
        float a3 = Xs[(row0 + 3) * S + k];
        float4 blo = *(float4*)(Ws + k * 64 + col0);
        float4 bhi = *(float4*)(Ws + k * 64 + col0 + 4);
        float b[8] = {blo.x, blo.y, blo.z, blo.w, bhi.x, bhi.y, bhi.z, bhi.w};
#pragma unroll
        for (int j = 0; j < 8; j++) {
            acc[0][j] = fmaf(a0, b[j], acc[0][j]);
            acc[1][j] = fmaf(a1, b[j], acc[1][j]);
            acc[2][j] = fmaf(a2, b[j], acc[2][j]);
            acc[3][j] = fmaf(a3, b[j], acc[3][j]);
        }
    }

#pragma unroll
    for (int i = 0; i < 4; i++) {
        int node = base + row0 + i;
        if (node < n) {
            float di = g_dinv[node];
            float f[8];
#pragma unroll
            for (int j = 0; j < 8; j++) f[j] = acc[i][j] * di;
            *(uint4*)(Z2h + (size_t)node * HID + col0) = pack_half8(f);
        }
    }
}

// ============ aggregate-2 (8 lanes/node, fp16) fused with mean pool =======
__global__ void k_agg_pool(const __half* __restrict__ zh,
                           const int* __restrict__ batch, int n) {
    int t    = blockIdx.x * blockDim.x + threadIdx.x;
    int node = t >> 3;
    int jg   = t & 7;
    if (node >= n) return;

    const uint4* z16 = (const uint4*)zh;
    float a[8] = {0.f,0.f,0.f,0.f,0.f,0.f,0.f,0.f};
    acc_half8(a, __ldg(z16 + (size_t)node * 8 + jg));

    const int dg = __ldg(g_deg + node);
    const int* ep = g_ell + (size_t)node * CAP;

    int i = 0;
    for (; i + 4 <= dg; i += 4) {
        int4 s4 = __ldg((const int4*)(ep + i));
        uint4 v0 = __ldg(z16 + (size_t)s4.x * 8 + jg);
        uint4 v1 = __ldg(z16 + (size_t)s4.y * 8 + jg);
        uint4 v2 = __ldg(z16 + (size_t)s4.z * 8 + jg);
        uint4 v3 = __ldg(z16 + (size_t)s4.w * 8 + jg);
        acc_half8(a, v0); acc_half8(a, v1);
        acc_half8(a, v2); acc_half8(a, v3);
    }
    for (; i < dg; i++) {
        int s0 = __ldg(ep + i);
        acc_half8(a, __ldg(z16 + (size_t)s0 * 8 + jg));
    }

    float di = g_dinv[node];
    float4 lo = make_float4(a[0]*di, a[1]*di, a[2]*di, a[3]*di);
    float4 hi = make_float4(a[4]*di, a[5]*di, a[6]*di, a[7]*di);
    int g = __ldg(batch + node);
    atomicAdd((float4*)(g_pool + g * HID + jg * 8), lo);
    atomicAdd((float4*)(g_pool + g * HID + jg * 8 + 4), hi);
    if (jg == 0) atomicAdd(&g_cnt[g], 1.0f);
}

__global__ void k_finalize(float* __restrict__ out,
                           const float* __restrict__ b2) {
    int t = blockIdx.x * blockDim.x + threadIdx.x;
    if (t >= GMAX * HID) return;
    int g = t >> 6, j = t & 63;
    out[t] = g_pool[t] / fmaxf(g_cnt[g], 1.0f) + b2[j];
}

// ================= launch (single stream, serial) =================
extern "C" void kernel_launch(void* const* d_in, const int* in_sizes, int n_in,
                              void* d_out, int out_size) {
    const float* x     = (const float*)d_in[0];
    const int*   eidx  = (const int*)d_in[1];
    const int*   batch = (const int*)d_in[2];
    const float* W1    = (const float*)d_in[3];
    const float* b1    = (const float*)d_in[4];
    const float* W2    = (const float*)d_in[5];
    const float* b2    = (const float*)d_in[6];
    float*       out   = (float*)d_out;

    const int n = in_sizes[0] / 128;
    const int E = in_sizes[1] / 2;
    const int* src = eidx;
    const int* dst = eidx + E;

    __half *z1h, *z2h;
    cudaGetSymbolAddress((void**)&z1h, g_z1h);
    cudaGetSymbolAddress((void**)&z2h, g_z2h);

    const int B = 256;
    const int NBn = (n + 255) / 256;
    const int NBe = (E + 255) / 256;
    const int gemm_grid = (n + 127) / 128;
    const int agg_grid  = (n * 8 + B - 1) / B;

    const int smemF = (128 * (64 + 4) + 64 * 64 + 64) * 4;     // 51456 B
    cudaFuncSetAttribute(k_gemm1_mma,
                         cudaFuncAttributeMaxDynamicSharedMemorySize, SM_G1);
    cudaFuncSetAttribute(k_agg_gemm2,
                         cudaFuncAttributeMaxDynamicSharedMemorySize, smemF);

    // ELL build (1 edge pass) + dinv + pool zeroing
    k_init<<<NBn, B>>>(n);
    k_ell_fill<<<NBe, B>>>(src, dst, E);
    k_dinv<<<NBn, B>>>(n);

    // layer-1 GEMM on tensor cores: z1 = (x@W1)*dinv -> fp16
    k_gemm1_mma<<<gemm_grid, 256, SM_G1>>>(x, W1, z1h, n);

    // fused aggregate-1 + transform + GEMM2 -> z2 (fp16)
    k_agg_gemm2<<<gemm_grid, 256, smemF>>>(z1h, W2, b1, z2h, n);

    // aggregate-2 fused with mean pool
    k_agg_pool<<<agg_grid, B>>>(z2h, batch, n);
    k_finalize<<<(GMAX * HID + B - 1) / B, B>>>(out, b2);
}

// round 16
// speedup vs baseline: 1.0700x; 1.0089x over previous
#include <cuda_runtime.h>
#include <cuda_fp16.h>
#include <cstdint>

#define NMAX 100000
#define EMAX 1600000
#define GMAX 128
#define HID  64
#define CAP  64      // ELL width; in-deg ~ Poisson(16), P(overflow) ~ 1e-13

// ---------------- scratch (no allocations allowed) ----------------
__device__ int    g_deg[NMAX];
__device__ int    g_ell[(size_t)NMAX * CAP];
__device__ __half g_z1h[(size_t)NMAX * HID];   // z1 = (x@W1)*dinv, fp16
__device__ __half g_z2h[(size_t)NMAX * HID];   // z2, fp16
__device__ float  g_pool[GMAX * HID];
__device__ float  g_cnt[GMAX];

// ---------------- helpers ----------------
__device__ __forceinline__ void acc_half8(float* a, uint4 v) {
    const __half2* h = (const __half2*)&v;
    float2 f0 = __half22float2(h[0]);
    float2 f1 = __half22float2(h[1]);
    float2 f2 = __half22float2(h[2]);
    float2 f3 = __half22float2(h[3]);
    a[0] += f0.x; a[1] += f0.y; a[2] += f1.x; a[3] += f1.y;
    a[4] += f2.x; a[5] += f2.y; a[6] += f3.x; a[7] += f3.y;
}
__device__ __forceinline__ uint4 pack_half8(const float* f) {
    __half2 h[4];
    h[0] = __floats2half2_rn(f[0], f[1]);
    h[1] = __floats2half2_rn(f[2], f[3]);
    h[2] = __floats2half2_rn(f[4], f[5]);
    h[3] = __floats2half2_rn(f[6], f[7]);
    return *(uint4*)h;
}
__device__ __forceinline__ void ldsm_x4(uint32_t* r, uint32_t addr) {
    asm volatile("ldmatrix.sync.aligned.m8n8.x4.shared.b16 {%0,%1,%2,%3}, [%4];"
                 : "=r"(r[0]), "=r"(r[1]), "=r"(r[2]), "=r"(r[3]) : "r"(addr));
}
__device__ __forceinline__ void ldsm_x4_t(uint32_t* r, uint32_t addr) {
    asm volatile("ldmatrix.sync.aligned.m8n8.x4.trans.shared.b16 {%0,%1,%2,%3}, [%4];"
                 : "=r"(r[0]), "=r"(r[1]), "=r"(r[2]), "=r"(r[3]) : "r"(addr));
}
__device__ __forceinline__ void mma16816(float* c, const uint32_t* a,
                                         uint32_t b0, uint32_t b1) {
    asm volatile(
        "mma.sync.aligned.m16n8k16.row.col.f32.f16.f16.f32 "
        "{%0,%1,%2,%3},{%4,%5,%6,%7},{%8,%9},{%0,%1,%2,%3};"
        : "+f"(c[0]), "+f"(c[1]), "+f"(c[2]), "+f"(c[3])
        : "r"(a[0]), "r"(a[1]), "r"(a[2]), "r"(a[3]), "r"(b0), "r"(b1));
}
__device__ __forceinline__ uint2 split_pack4(float4 v) {
    __half h0 = __float2half(v.x), h1 = __float2half(v.y);
    __half h2 = __float2half(v.z), h3 = __float2half(v.w);
    uint2 r;
    r.x = (uint32_t)__half_as_ushort(h0) | ((uint32_t)__half_as_ushort(h1) << 16);
    r.y = (uint32_t)__half_as_ushort(h2) | ((uint32_t)__half_as_ushort(h3) << 16);
    return r;
}

// ================= graph build (ELL, one edge pass) =================
__global__ void k_init(int n) {
    int i = blockIdx.x * blockDim.x + threadIdx.x;
    if (i < n) g_deg[i] = 0;
    if (i < GMAX * HID) g_pool[i] = 0.f;
    if (i < GMAX) g_cnt[i] = 0.f;
}
__global__ void k_ell_fill(const int* __restrict__ src,
                           const int* __restrict__ dst, int E) {
    int e = blockIdx.x * blockDim.x + threadIdx.x;
    if (e >= E) return;
    int d = dst[e];
    int p = atomicAdd(&g_deg[d], 1);
    g_ell[(size_t)d * CAP + p] = src[e];
}

// ================= tensor-core GEMM1 (plain fp16 HMMA) =================
// z1[node,:] = (x[node,:] @ W1) * dinv[node] -> fp16
// W: 72-half rows (144B stride); A: 136-half rows (272B = 17x16B, odd ->
// ldmatrix conflict-free). Full K staged in ONE burst (MLP=16/thread).
#define SWW 72
#define SWA 136
#define OFF_W 0
#define OFF_A 18432
#define SM_G1 (18432 + 34816)      // 53248 B

__global__ void __launch_bounds__(256)
k_gemm1_mma(const float* __restrict__ X,
            const float* __restrict__ Wg,     // [128][64] fp32
            __half* __restrict__ Zh, int n) {
    extern __shared__ char sm[];
    const uint32_t sbase = (uint32_t)__cvta_generic_to_shared(sm);
    const int tid  = threadIdx.x;
    const int wid  = tid >> 5;
    const int lane = tid & 31;
    const int base = blockIdx.x * 128;

    // ---- stage W (K=128 rows x 64 cols): fp32 -> fp16 ----
    for (int i = tid; i < 128 * 16; i += 256) {
        int row = i >> 4, c4 = i & 15;
        float4 w = ((const float4*)Wg)[i];
        *(uint2*)(sm + OFF_W + (row * SWW + c4 * 4) * 2) = split_pack4(w);
    }

    // ---- stage full A (128 rows x 128 cols) in one burst ----
    for (int i = tid; i < 128 * 32; i += 256) {      // 16 float4 per thread
        int m = i >> 5, c4 = i & 31;
        int node = base + m;
        float4 v = make_float4(0.f, 0.f, 0.f, 0.f);
        if (node < n)
            v = ((const float4*)(X + (size_t)node * 128))[c4];
        *(uint2*)(sm + OFF_A + (m * SWA + c4 * 4) * 2) = split_pack4(v);
    }
    __syncthreads();

    const int m0 = wid * 16;
    float c[8][4];
#pragma unroll
    for (int j = 0; j < 8; j++)
#pragma unroll
        for (int q = 0; q < 4; q++) c[j][q] = 0.f;

    const int a_row = m0 + (lane & 15);
    const int a_koff = (lane >> 4) << 3;
    const int b_rowoff = ((lane & 8) ? 8 : 0) + (lane & 7);
    const int b_noff = (lane >> 4) << 3;

#pragma unroll
    for (int ks = 0; ks < 8; ks++) {
        const int k0 = ks * 16;
        uint32_t ah[4];
        ldsm_x4(ah, sbase + OFF_A + (a_row * SWA + k0 + a_koff) * 2);

        const int b_row = k0 + b_rowoff;
#pragma unroll
        for (int np = 0; np < 4; np++) {
            uint32_t bh[4];
            ldsm_x4_t(bh, sbase + OFF_W + (b_row * SWW + np * 16 + b_noff) * 2);
            mma16816(c[2 * np],     ah, bh[0], bh[1]);
            mma16816(c[2 * np + 1], ah, bh[2], bh[3]);
        }
    }

    // ---- epilogue: scale by dinv (from deg), pack fp16, store ----
    const int r0 = m0 + (lane >> 2);
    const int cc = (lane & 3) * 2;
    int node0 = base + r0;
    int node1 = node0 + 8;
    float d0 = (node0 < n) ? rsqrtf((float)__ldg(g_deg + node0) + 1.0f) : 0.f;
    float d1 = (node1 < n) ? rsqrtf((float)__ldg(g_deg + node1) + 1.0f) : 0.f;
#pragma unroll
    for (int j = 0; j < 8; j++) {
        int col = j * 8 + cc;
        if (node0 < n) {
            __half2 h = __floats2half2_rn(c[j][0] * d0, c[j][1] * d0);
            *(__half2*)(Zh + (size_t)node0 * HID + col) = h;
        }
        if (node1 < n) {
            __half2 h = __floats2half2_rn(c[j][2] * d1, c[j][3] * d1);
            *(__half2*)(Zh + (size_t)node1 * HID + col) = h;
        }
    }
}

// ---- gather core: 8 lanes/node, unroll-8 (2 idx int4 + 8 gathers in flight)
// Returns deg so callers can derive dinv without reloading.
__device__ __forceinline__ int gather_node(float* a, const uint4* z16,
                                           int node, int jg) {
    acc_half8(a, __ldg(z16 + (size_t)node * 8 + jg));      // self term

    const int dg = __ldg(g_deg + node);
    const int* ep = g_ell + (size_t)node * CAP;

    int i = 0;
    for (; i + 8 <= dg; i += 8) {
        int4 sa = __ldg((const int4*)(ep + i));
        int4 sb = __ldg((const int4*)(ep + i + 4));
        uint4 v0 = __ldg(z16 + (size_t)sa.x * 8 + jg);
        uint4 v1 = __ldg(z16 + (size_t)sa.y * 8 + jg);
        uint4 v2 = __ldg(z16 + (size_t)sa.z * 8 + jg);
        uint4 v3 = __ldg(z16 + (size_t)sa.w * 8 + jg);
        uint4 v4 = __ldg(z16 + (size_t)sb.x * 8 + jg);
        uint4 v5 = __ldg(z16 + (size_t)sb.y * 8 + jg);
        uint4 v6 = __ldg(z16 + (size_t)sb.z * 8 + jg);
        uint4 v7 = __ldg(z16 + (size_t)sb.w * 8 + jg);
        acc_half8(a, v0); acc_half8(a, v1);
        acc_half8(a, v2); acc_half8(a, v3);
        acc_half8(a, v4); acc_half8(a, v5);
        acc_half8(a, v6); acc_half8(a, v7);
    }
    if (i + 4 <= dg) {
        int4 s4 = __ldg((const int4*)(ep + i));
        uint4 v0 = __ldg(z16 + (size_t)s4.x * 8 + jg);
        uint4 v1 = __ldg(z16 + (size_t)s4.y * 8 + jg);
        uint4 v2 = __ldg(z16 + (size_t)s4.z * 8 + jg);
        uint4 v3 = __ldg(z16 + (size_t)s4.w * 8 + jg);
        acc_half8(a, v0); acc_half8(a, v1);
        acc_half8(a, v2); acc_half8(a, v3);
        i += 4;
    }
    for (; i < dg; i++) {
        int s0 = __ldg(ep + i);
        acc_half8(a, __ldg(z16 + (size_t)s0 * 8 + jg));
    }
    return dg;
}

// ========== FUSED: aggregate-1 + input-transform + GEMM2 ==========
__global__ void __launch_bounds__(256)
k_agg_gemm2(const __half* __restrict__ z1h,
            const float* __restrict__ W2,
            const float* __restrict__ b1,
            __half* __restrict__ Z2h, int n) {
    constexpr int BM = 128;
    constexpr int K  = 64;
    constexpr int S  = K + 4;
    extern __shared__ float smf[];
    float* Xs = smf;                 // [128][68]
    float* Ws = smf + BM * S;        // [64][64]
    float* bs = Ws + K * 64;         // [64]

    const int tid  = threadIdx.x;
    const int base = blockIdx.x * BM;

    for (int i = tid; i < K * 16; i += 256)
        ((float4*)Ws)[i] = ((const float4*)W2)[i];
    if (tid < 64) bs[tid] = b1[tid];

    const uint4* z16 = (const uint4*)z1h;
#pragma unroll
    for (int p = 0; p < 4; p++) {
        int t  = tid + p * 256;
        int m  = t >> 3;
        int jg = t & 7;
        int node = base + m;
        float a[8] = {0.f,0.f,0.f,0.f,0.f,0.f,0.f,0.f};
        if (node < n) {
            int dg = gather_node(a, z16, node, jg);
            float dn = rsqrtf((float)dg + 1.0f);
            int k0 = jg * 8;
#pragma unroll
            for (int j = 0; j < 8; j++)
                a[j] = fmaxf(fmaf(a[j], dn, bs[k0 + j]), 0.f);
        }
        *(float4*)(Xs + m * S + jg * 8)     = make_float4(a[0], a[1], a[2], a[3]);
        *(float4*)(Xs + m * S + jg * 8 + 4) = make_float4(a[4], a[5], a[6], a[7]);
    }
    __syncthreads();

    // ---- phase B: tile GEMM, epilogue * dinv -> fp16 ----
    const int row0 = (tid >> 3) * 4;
    const int col0 = (tid & 7) * 8;

    float acc[4][8];
#pragma unroll
    for (int i = 0; i < 4; i++)
#pragma unroll
        for (int j = 0; j < 8; j++) acc[i][j] = 0.f;

#pragma unroll 4
    for (int k = 0; k < K; k++) {
        float a0 = Xs[(row0 + 0) * S + k];
        float a1 = Xs[(row0 + 1) * S + k];
        float a2 = Xs[(row0 + 2) * S + k];
        float a3 = Xs[(row0 + 3) * S + k];
        float4 blo = *(float4*)(Ws + k * 64 + col0);
        float4 bhi = *(float4*)(Ws + k * 64 + col0 + 4);
        float b[8] = {blo.x, blo.y, blo.z, blo.w, bhi.x, bhi.y, bhi.z, bhi.w};
#pragma unroll
        for (int j = 0; j < 8; j++) {
            acc[0][j] = fmaf(a0, b[j], acc[0][j]);
            acc[1][j] = fmaf(a1, b[j], acc[1][j]);
            acc[2][j] = fmaf(a2, b[j], acc[2][j]);
            acc[3][j] = fmaf(a3, b[j], acc[3][j]);
        }
    }

#pragma unroll
    for (int i = 0; i < 4; i++) {
        int node = base + row0 + i;
        if (node < n) {
            float di = rsqrtf((float)__ldg(g_deg + node) + 1.0f);
            float f[8];
#pragma unroll
            for (int j = 0; j < 8; j++) f[j] = acc[i][j] * di;
            *(uint4*)(Z2h + (size_t)node * HID + col0) = pack_half8(f);
        }
    }
}

// ============ aggregate-2 (8 lanes/node, fp16) fused with mean pool =======
__global__ void __launch_bounds__(256)
k_agg_pool(const __half* __restrict__ zh,
           const int* __restrict__ batch, int n) {
    int t    = blockIdx.x * blockDim.x + threadIdx.x;
    int node = t >> 3;
    int jg   = t & 7;
    if (node >= n) return;

    const uint4* z16 = (const uint4*)zh;
    float a[8] = {0.f,0.f,0.f,0.f,0.f,0.f,0.f,0.f};
    int dg = gather_node(a, z16, node, jg);

    float di = rsqrtf((float)dg + 1.0f);
    float4 lo = make_float4(a[0]*di, a[1]*di, a[2]*di, a[3]*di);
    float4 hi = make_float4(a[4]*di, a[5]*di, a[6]*di, a[7]*di);
    int g = __ldg(batch + node);
    atomicAdd((float4*)(g_pool + g * HID + jg * 8), lo);
    atomicAdd((float4*)(g_pool + g * HID + jg * 8 + 4), hi);
    if (jg == 0) atomicAdd(&g_cnt[g], 1.0f);
}

__global__ void k_finalize(float* __restrict__ out,
                           const float* __restrict__ b2) {
    int t = blockIdx.x * blockDim.x + threadIdx.x;
    if (t >= GMAX * HID) return;
    int g = t >> 6, j = t & 63;
    out[t] = g_pool[t] / fmaxf(g_cnt[g], 1.0f) + b2[j];
}

// ================= launch (single stream, serial) =================
extern "C" void kernel_launch(void* const* d_in, const int* in_sizes, int n_in,
                              void* d_out, int out_size) {
    const float* x     = (const float*)d_in[0];
    const int*   eidx  = (const int*)d_in[1];
    const int*   batch = (const int*)d_in[2];
    const float* W1    = (const float*)d_in[3];
    const float* b1    = (const float*)d_in[4];
    const float* W2    = (const float*)d_in[5];
    const float* b2    = (const float*)d_in[6];
    float*       out   = (float*)d_out;

    const int n = in_sizes[0] / 128;
    const int E = in_sizes[1] / 2;
    const int* src = eidx;
    const int* dst = eidx + E;

    __half *z1h, *z2h;
    cudaGetSymbolAddress((void**)&z1h, g_z1h);
    cudaGetSymbolAddress((void**)&z2h, g_z2h);

    const int B = 256;
    const int NBn = (n + 255) / 256;
    const int NBe = (E + 255) / 256;
    const int gemm_grid = (n + 127) / 128;
    const int agg_grid  = (n * 8 + B - 1) / B;

    const int smemF = (128 * (64 + 4) + 64 * 64 + 64) * 4;     // 51456 B
    cudaFuncSetAttribute(k_gemm1_mma,
                         cudaFuncAttributeMaxDynamicSharedMemorySize, SM_G1);
    cudaFuncSetAttribute(k_agg_gemm2,
                         cudaFuncAttributeMaxDynamicSharedMemorySize, smemF);

    // ELL build (1 edge pass) + pool zeroing
    k_init<<<NBn, B>>>(n);
    k_ell_fill<<<NBe, B>>>(src, dst, E);

    // layer-1 GEMM on tensor cores: z1 = (x@W1)*dinv -> fp16
    k_gemm1_mma<<<gemm_grid, 256, SM_G1>>>(x, W1, z1h, n);

    // fused aggregate-1 + transform + GEMM2 -> z2 (fp16)
    k_agg_gemm2<<<gemm_grid, 256, smemF>>>(z1h, W2, b1, z2h, n);

    // aggregate-2 fused with mean pool
    k_agg_pool<<<agg_grid, B>>>(z2h, batch, n);
    k_finalize<<<(GMAX * HID + B - 1) / B, B>>>(out, b2);
}

// round 17
// speedup vs baseline: 1.1457x; 1.0707x over previous
#include <cuda_runtime.h>
#include <cuda_fp16.h>
#include <cstdint>

#define NMAX 100000
#define EMAX 1600000
#define GMAX 128
#define HID  64
#define CAP  64      // ELL width; in-deg ~ Poisson(16), P(overflow) ~ 1e-13

// ---------------- scratch (no allocations allowed) ----------------
__device__ int    g_deg[NMAX];
__device__ int    g_ell[(size_t)NMAX * CAP];
__device__ __half g_z1h[(size_t)NMAX * HID];   // z1 = (x@W1)*dinv, fp16
__device__ __half g_z2h[(size_t)NMAX * HID];   // z2, fp16
__device__ float  g_pool[GMAX * HID];
__device__ float  g_cnt[GMAX];

// ---------------- helpers ----------------
__device__ __forceinline__ void acc_half8(float* a, uint4 v) {
    const __half2* h = (const __half2*)&v;
    float2 f0 = __half22float2(h[0]);
    float2 f1 = __half22float2(h[1]);
    float2 f2 = __half22float2(h[2]);
    float2 f3 = __half22float2(h[3]);
    a[0] += f0.x; a[1] += f0.y; a[2] += f1.x; a[3] += f1.y;
    a[4] += f2.x; a[5] += f2.y; a[6] += f3.x; a[7] += f3.y;
}
__device__ __forceinline__ uint4 pack_half8(const float* f) {
    __half2 h[4];
    h[0] = __floats2half2_rn(f[0], f[1]);
    h[1] = __floats2half2_rn(f[2], f[3]);
    h[2] = __floats2half2_rn(f[4], f[5]);
    h[3] = __floats2half2_rn(f[6], f[7]);
    return *(uint4*)h;
}
__device__ __forceinline__ void ldsm_x4(uint32_t* r, uint32_t addr) {
    asm volatile("ldmatrix.sync.aligned.m8n8.x4.shared.b16 {%0,%1,%2,%3}, [%4];"
                 : "=r"(r[0]), "=r"(r[1]), "=r"(r[2]), "=r"(r[3]) : "r"(addr));
}
__device__ __forceinline__ void ldsm_x4_t(uint32_t* r, uint32_t addr) {
    asm volatile("ldmatrix.sync.aligned.m8n8.x4.trans.shared.b16 {%0,%1,%2,%3}, [%4];"
                 : "=r"(r[0]), "=r"(r[1]), "=r"(r[2]), "=r"(r[3]) : "r"(addr));
}
__device__ __forceinline__ void mma16816(float* c, const uint32_t* a,
                                         uint32_t b0, uint32_t b1) {
    asm volatile(
        "mma.sync.aligned.m16n8k16.row.col.f32.f16.f16.f32 "
        "{%0,%1,%2,%3},{%4,%5,%6,%7},{%8,%9},{%0,%1,%2,%3};"
        : "+f"(c[0]), "+f"(c[1]), "+f"(c[2]), "+f"(c[3])
        : "r"(a[0]), "r"(a[1]), "r"(a[2]), "r"(a[3]), "r"(b0), "r"(b1));
}
__device__ __forceinline__ uint2 split_pack4(float4 v) {
    __half h0 = __float2half(v.x), h1 = __float2half(v.y);
    __half h2 = __float2half(v.z), h3 = __float2half(v.w);
    uint2 r;
    r.x = (uint32_t)__half_as_ushort(h0) | ((uint32_t)__half_as_ushort(h1) << 16);
    r.y = (uint32_t)__half_as_ushort(h2) | ((uint32_t)__half_as_ushort(h3) << 16);
    return r;
}

// ================= graph build (ELL, one edge pass) =================
__global__ void k_init(int n) {
    int i = blockIdx.x * blockDim.x + threadIdx.x;
    if (i < n) g_deg[i] = 0;
    if (i < GMAX * HID) g_pool[i] = 0.f;
    if (i < GMAX) g_cnt[i] = 0.f;
}
__global__ void k_ell_fill(const int* __restrict__ src,
                           const int* __restrict__ dst, int E) {
    int e = blockIdx.x * blockDim.x + threadIdx.x;
    if (e >= E) return;
    int d = dst[e];
    int p = atomicAdd(&g_deg[d], 1);
    g_ell[(size_t)d * CAP + p] = src[e];
}

// ================= tensor-core GEMM1 (plain fp16 HMMA) =================
// z1[node,:] = (x[node,:] @ W1) * dinv[node] -> fp16
#define SWW 72
#define SWA 136
#define OFF_W 0
#define OFF_A 18432
#define SM_G1 (18432 + 34816)      // 53248 B

__global__ void __launch_bounds__(256)
k_gemm1_mma(const float* __restrict__ X,
            const float* __restrict__ Wg,     // [128][64] fp32
            __half* __restrict__ Zh, int n) {
    extern __shared__ char sm[];
    const uint32_t sbase = (uint32_t)__cvta_generic_to_shared(sm);
    const int tid  = threadIdx.x;
    const int wid  = tid >> 5;
    const int lane = tid & 31;
    const int base = blockIdx.x * 128;

    for (int i = tid; i < 128 * 16; i += 256) {
        int row = i >> 4, c4 = i & 15;
        float4 w = ((const float4*)Wg)[i];
        *(uint2*)(sm + OFF_W + (row * SWW + c4 * 4) * 2) = split_pack4(w);
    }
    for (int i = tid; i < 128 * 32; i += 256) {
        int m = i >> 5, c4 = i & 31;
        int node = base + m;
        float4 v = make_float4(0.f, 0.f, 0.f, 0.f);
        if (node < n)
            v = ((const float4*)(X + (size_t)node * 128))[c4];
        *(uint2*)(sm + OFF_A + (m * SWA + c4 * 4) * 2) = split_pack4(v);
    }
    __syncthreads();

    const int m0 = wid * 16;
    float c[8][4];
#pragma unroll
    for (int j = 0; j < 8; j++)
#pragma unroll
        for (int q = 0; q < 4; q++) c[j][q] = 0.f;

    const int a_row = m0 + (lane & 15);
    const int a_koff = (lane >> 4) << 3;
    const int b_rowoff = ((lane & 8) ? 8 : 0) + (lane & 7);
    const int b_noff = (lane >> 4) << 3;

#pragma unroll
    for (int ks = 0; ks < 8; ks++) {
        const int k0 = ks * 16;
        uint32_t ah[4];
        ldsm_x4(ah, sbase + OFF_A + (a_row * SWA + k0 + a_koff) * 2);
        const int b_row = k0 + b_rowoff;
#pragma unroll
        for (int np = 0; np < 4; np++) {
            uint32_t bh[4];
            ldsm_x4_t(bh, sbase + OFF_W + (b_row * SWW + np * 16 + b_noff) * 2);
            mma16816(c[2 * np],     ah, bh[0], bh[1]);
            mma16816(c[2 * np + 1], ah, bh[2], bh[3]);
        }
    }

    const int r0 = m0 + (lane >> 2);
    const int cc = (lane & 3) * 2;
    int node0 = base + r0;
    int node1 = node0 + 8;
    float d0 = (node0 < n) ? rsqrtf((float)__ldg(g_deg + node0) + 1.0f) : 0.f;
    float d1 = (node1 < n) ? rsqrtf((float)__ldg(g_deg + node1) + 1.0f) : 0.f;
#pragma unroll
    for (int j = 0; j < 8; j++) {
        int col = j * 8 + cc;
        if (node0 < n) {
            __half2 h = __floats2half2_rn(c[j][0] * d0, c[j][1] * d0);
            *(__half2*)(Zh + (size_t)node0 * HID + col) = h;
        }
        if (node1 < n) {
            __half2 h = __floats2half2_rn(c[j][2] * d1, c[j][3] * d1);
            *(__half2*)(Zh + (size_t)node1 * HID + col) = h;
        }
    }
}

// ---- gather core: 8 lanes/node, unroll-8; returns deg ----
__device__ __forceinline__ int gather_node(float* a, const uint4* z16,
                                           int node, int jg) {
    acc_half8(a, __ldg(z16 + (size_t)node * 8 + jg));      // self term

    const int dg = __ldg(g_deg + node);
    const int* ep = g_ell + (size_t)node * CAP;

    int i = 0;
    for (; i + 8 <= dg; i += 8) {
        int4 sa = __ldg((const int4*)(ep + i));
        int4 sb = __ldg((const int4*)(ep + i + 4));
        uint4 v0 = __ldg(z16 + (size_t)sa.x * 8 + jg);
        uint4 v1 = __ldg(z16 + (size_t)sa.y * 8 + jg);
        uint4 v2 = __ldg(z16 + (size_t)sa.z * 8 + jg);
        uint4 v3 = __ldg(z16 + (size_t)sa.w * 8 + jg);
        uint4 v4 = __ldg(z16 + (size_t)sb.x * 8 + jg);
        uint4 v5 = __ldg(z16 + (size_t)sb.y * 8 + jg);
        uint4 v6 = __ldg(z16 + (size_t)sb.z * 8 + jg);
        uint4 v7 = __ldg(z16 + (size_t)sb.w * 8 + jg);
        acc_half8(a, v0); acc_half8(a, v1);
        acc_half8(a, v2); acc_half8(a, v3);
        acc_half8(a, v4); acc_half8(a, v5);
        acc_half8(a, v6); acc_half8(a, v7);
    }
    if (i + 4 <= dg) {
        int4 s4 = __ldg((const int4*)(ep + i));
        uint4 v0 = __ldg(z16 + (size_t)s4.x * 8 + jg);
        uint4 v1 = __ldg(z16 + (size_t)s4.y * 8 + jg);
        uint4 v2 = __ldg(z16 + (size_t)s4.z * 8 + jg);
        uint4 v3 = __ldg(z16 + (size_t)s4.w * 8 + jg);
        acc_half8(a, v0); acc_half8(a, v1);
        acc_half8(a, v2); acc_half8(a, v3);
        i += 4;
    }
    for (; i < dg; i++) {
        int s0 = __ldg(ep + i);
        acc_half8(a, __ldg(z16 + (size_t)s0 * 8 + jg));
    }
    return dg;
}

// ========== FUSED: aggregate-1 + transform + tensor-core GEMM2 ==========
// Phase A: x2 = relu(dinv*S + b1) -> fp16 ldmatrix tile in smem.
// Phase B: z2 = (x2 @ W2) * dinv -> fp16, via m16n8k16 HMMA (K=64).
#define SW2 72
#define OFF2_W 0                    // [64][72] half = 9216 B
#define OFF2_X 9216                 // [128][72] half = 18432 B
#define OFF2_B 27648                // [64] float = 256 B
#define SM_F   27904

__global__ void __launch_bounds__(256)
k_agg_gemm2(const __half* __restrict__ z1h,
            const float* __restrict__ W2,     // [64][64] fp32
            const float* __restrict__ b1,
            __half* __restrict__ Z2h, int n) {
    extern __shared__ char sm[];
    const uint32_t sbase = (uint32_t)__cvta_generic_to_shared(sm);
    float* bs = (float*)(sm + OFF2_B);

    const int tid  = threadIdx.x;
    const int wid  = tid >> 5;
    const int lane = tid & 31;
    const int base = blockIdx.x * 128;

    // stage W2 as fp16 [64][72]
    for (int i = tid; i < 64 * 16; i += 256) {
        int row = i >> 4, c4 = i & 15;
        float4 w = ((const float4*)W2)[i];
        *(uint2*)(sm + OFF2_W + (row * SW2 + c4 * 4) * 2) = split_pack4(w);
    }
    if (tid < 64) bs[tid] = b1[tid];
    __syncthreads();    // bs must be visible before phase A uses it

    // ---- phase A: gather-aggregate -> relu -> fp16 X tile ----
    const uint4* z16 = (const uint4*)z1h;
#pragma unroll
    for (int p = 0; p < 4; p++) {
        int t  = tid + p * 256;
        int m  = t >> 3;
        int jg = t & 7;
        int node = base + m;
        float a[8] = {0.f,0.f,0.f,0.f,0.f,0.f,0.f,0.f};
        if (node < n) {
            int dg = gather_node(a, z16, node, jg);
            float dn = rsqrtf((float)dg + 1.0f);
            int k0 = jg * 8;
#pragma unroll
            for (int j = 0; j < 8; j++)
                a[j] = fmaxf(fmaf(a[j], dn, bs[k0 + j]), 0.f);
        }
        *(uint4*)(sm + OFF2_X + (m * SW2 + jg * 8) * 2) = pack_half8(a);
    }
    __syncthreads();

    // ---- phase B: HMMA GEMM (128x64 @ 64x64), epilogue * dinv -> fp16 ----
    const int m0 = wid * 16;
    float c[8][4];
#pragma unroll
    for (int j = 0; j < 8; j++)
#pragma unroll
        for (int q = 0; q < 4; q++) c[j][q] = 0.f;

    const int a_row = m0 + (lane & 15);
    const int a_koff = (lane >> 4) << 3;
    const int b_rowoff = ((lane & 8) ? 8 : 0) + (lane & 7);
    const int b_noff = (lane >> 4) << 3;

#pragma unroll
    for (int ks = 0; ks < 4; ks++) {
        const int k0 = ks * 16;
        uint32_t ah[4];
        ldsm_x4(ah, sbase + OFF2_X + (a_row * SW2 + k0 + a_koff) * 2);
        const int b_row = k0 + b_rowoff;
#pragma unroll
        for (int np = 0; np < 4; np++) {
            uint32_t bh[4];
            ldsm_x4_t(bh, sbase + OFF2_W + (b_row * SW2 + np * 16 + b_noff) * 2);
            mma16816(c[2 * np],     ah, bh[0], bh[1]);
            mma16816(c[2 * np + 1], ah, bh[2], bh[3]);
        }
    }

    const int r0 = m0 + (lane >> 2);
    const int cc = (lane & 3) * 2;
    int node0 = base + r0;
    int node1 = node0 + 8;
    float d0 = (node0 < n) ? rsqrtf((float)__ldg(g_deg + node0) + 1.0f) : 0.f;
    float d1 = (node1 < n) ? rsqrtf((float)__ldg(g_deg + node1) + 1.0f) : 0.f;
#pragma unroll
    for (int j = 0; j < 8; j++) {
        int col = j * 8 + cc;
        if (node0 < n) {
            __half2 h = __floats2half2_rn(c[j][0] * d0, c[j][1] * d0);
            *(__half2*)(Z2h + (size_t)node0 * HID + col) = h;
        }
        if (node1 < n) {
            __half2 h = __floats2half2_rn(c[j][2] * d1, c[j][3] * d1);
            *(__half2*)(Z2h + (size_t)node1 * HID + col) = h;
        }
    }
}

// ============ aggregate-2 (8 lanes/node, fp16) fused with mean pool =======
__global__ void __launch_bounds__(256)
k_agg_pool(const __half* __restrict__ zh,
           const int* __restrict__ batch, int n) {
    int t    = blockIdx.x * blockDim.x + threadIdx.x;
    int node = t >> 3;
    int jg   = t & 7;
    if (node >= n) return;

    const uint4* z16 = (const uint4*)zh;
    float a[8] = {0.f,0.f,0.f,0.f,0.f,0.f,0.f,0.f};
    int dg = gather_node(a, z16, node, jg);

    float di = rsqrtf((float)dg + 1.0f);
    float4 lo = make_float4(a[0]*di, a[1]*di, a[2]*di, a[3]*di);
    float4 hi = make_float4(a[4]*di, a[5]*di, a[6]*di, a[7]*di);
    int g = __ldg(batch + node);
    atomicAdd((float4*)(g_pool + g * HID + jg * 8), lo);
    atomicAdd((float4*)(g_pool + g * HID + jg * 8 + 4), hi);
    if (jg == 0) atomicAdd(&g_cnt[g], 1.0f);
}

__global__ void k_finalize(float* __restrict__ out,
                           const float* __restrict__ b2) {
    int t = blockIdx.x * blockDim.x + threadIdx.x;
    if (t >= GMAX * HID) return;
    int g = t >> 6, j = t & 63;
    out[t] = g_pool[t] / fmaxf(g_cnt[g], 1.0f) + b2[j];
}

// ================= launch (single stream, serial) =================
extern "C" void kernel_launch(void* const* d_in, const int* in_sizes, int n_in,
                              void* d_out, int out_size) {
    const float* x     = (const float*)d_in[0];
    const int*   eidx  = (const int*)d_in[1];
    const int*   batch = (const int*)d_in[2];
    const float* W1    = (const float*)d_in[3];
    const float* b1    = (const float*)d_in[4];
    const float* W2    = (const float*)d_in[5];
    const float* b2    = (const float*)d_in[6];
    float*       out   = (float*)d_out;

    const int n = in_sizes[0] / 128;
    const int E = in_sizes[1] / 2;
    const int* src = eidx;
    const int* dst = eidx + E;

    __half *z1h, *z2h;
    cudaGetSymbolAddress((void**)&z1h, g_z1h);
    cudaGetSymbolAddress((void**)&z2h, g_z2h);

    const int B = 256;
    const int NBn = (n + 255) / 256;
    const int NBe = (E + 255) / 256;
    const int gemm_grid = (n + 127) / 128;
    const int agg_grid  = (n * 8 + B - 1) / B;

    cudaFuncSetAttribute(k_gemm1_mma,
                         cudaFuncAttributeMaxDynamicSharedMemorySize, SM_G1);
    cudaFuncSetAttribute(k_agg_gemm2,
                         cudaFuncAttributeMaxDynamicSharedMemorySize, SM_F);

    // ELL build (1 edge pass) + pool zeroing
    k_init<<<NBn, B>>>(n);
    k_ell_fill<<<NBe, B>>>(src, dst, E);

    // layer-1 GEMM on tensor cores: z1 = (x@W1)*dinv -> fp16
    k_gemm1_mma<<<gemm_grid, 256, SM_G1>>>(x, W1, z1h, n);

    // fused aggregate-1 + transform + tensor-core GEMM2 -> z2 (fp16)
    k_agg_gemm2<<<gemm_grid, 256, SM_F>>>(z1h, W2, b1, z2h, n);

    // aggregate-2 fused with mean pool
    k_agg_pool<<<agg_grid, B>>>(z2h, batch, n);
    k_finalize<<<(GMAX * HID + B - 1) / B, B>>>(out, b2);
}